// round 6
// baseline (speedup 1.0000x reference)
#include <cuda_runtime.h>
#include <cstdint>

// Problem constants
#define TT 128
#define SS 512
#define BB 512
#define GRID_F 148          // one CTA per SM, single wave
#define ENG 3               // 128-thread engines per CTA
#define NENG (GRID_F*ENG)   // 444 engines

// E rows kept in registers vs shared memory (spill avoidance):
//   i in [0,104)   -> 52 f32x2 pairs in registers (104 regs)
//   i in [104,128) -> 24 rows in SMEM, packed as float4 quads per column
#define REG_PAIRS 52
#define SME_ROWS  24
#define SME_QUADS 6   // 24 rows / 4

__device__ float g_res[BB];   // per-batch (numerator - denominator)

__device__ __forceinline__ float fex2(float x){ float r; asm("ex2.approx.f32 %0,%1;":"=f"(r):"f"(x)); return r; }
__device__ __forceinline__ float flg2(float x){ float r; asm("lg2.approx.f32 %0,%1;":"=f"(r):"f"(x)); return r; }

#define FMA2(d,a,b,c) asm("fma.rn.f32x2 %0,%1,%2,%3;":"=l"(d):"l"(a),"l"(b),"l"(c))
#define ADD2(d,a,b)   asm("add.rn.f32x2 %0,%1,%2;":"=l"(d):"l"(a),"l"(b))

#define L2E 1.4426950408889634f
#define LN2 0.6931471805599453f

// ---------------------------------------------------------------------------
// Forward algorithm + numerator. One 128-thread engine per batch sequence.
// Thread j owns column E[:,j] = exp(trans[:,j]): 52 pairs in regs, 24 values
// from CTA-shared SMEM (E is batch-invariant, one copy per CTA).
// Per step: p_i = exp(u_i) broadcast via smem; GEMV acc_j = sum_i p_i*E_ij
// with packed f32x2 FMAs; u'_j = em_j + log(acc_j) - K, C += K, where K is
// thread 0's u from the previous step (delayed renormalizer).
// ---------------------------------------------------------------------------
__global__ void __launch_bounds__(384,1) crf_forward(
    const float* __restrict__ em, const int* __restrict__ tags,
    const int* __restrict__ mask, const float* __restrict__ startt,
    const float* __restrict__ endt, const float* __restrict__ trans)
{
  __shared__ float4 sE[SME_QUADS][TT];     // 12 KB, shared by all engines
  __shared__ float  pbuf[ENG][2][TT];
  __shared__ float  kbuf[ENG][2];
  __shared__ float  red[ENG][8];

  const int tid  = threadIdx.x;
  const int eng  = tid >> 7;      // 0..2
  const int j    = tid & 127;     // state index owned by this thread
  const int lane = tid & 31;
  const int wrp  = (tid & 127) >> 5;
  const int barid = eng + 1;      // named barrier per engine

  // ---- CTA-cooperative init of SMEM E rows [104,128) ----
  for (int idx = tid; idx < SME_ROWS*TT; idx += 384){
    int r  = idx >> 7;            // 0..23  -> i = 104 + r
    int jc = idx & 127;
    float e = fex2(trans[(104 + r)*TT + jc] * L2E);
    ((float*)sE)[((r >> 2)*TT + jc)*4 + (r & 3)] = e;
  }

  // ---- per-thread register E pairs, i in [0,104) ----
  unsigned long long E2[REG_PAIRS];
  #pragma unroll
  for (int q = 0; q < REG_PAIRS; ++q){
    float e0 = fex2(trans[(2*q  )*TT + j] * L2E);
    float e1 = fex2(trans[(2*q+1)*TT + j] * L2E);
    unsigned long long pk;
    asm("mov.b64 %0,{%1,%2};":"=l"(pk):"f"(e0),"f"(e1));
    E2[q] = pk;
  }
  const float endj = endt[j];
  const float stj  = startt[j];

  const uint32_t pb0   = (uint32_t)__cvta_generic_to_shared(&pbuf[eng][0][0]);
  const uint32_t sEb   = (uint32_t)__cvta_generic_to_shared(&sE[0][0]) + j*16;

  __syncthreads();   // sE ready for all engines

  const int ge = eng*GRID_F + blockIdx.x;   // global engine id (0..443)

  for (int b = ge; b < BB; b += NENG){
    asm volatile("bar.sync %0,128;"::"r"(barid):"memory");

    const float* ebb = em + (long long)b*SS*TT;    // batch base
    const float* eb  = ebb + j;                    // column-j view
    const int*   mb  = mask + b*SS;
    const int*   tg  = tags + b*SS;

    // ---------------- numerator (gather path score), trivial cost ----------
    float nacc = 0.f; int ncnt = 0;
    for (int s = j; s < SS; s += TT){
      int m = mb[s];
      ncnt += (m > 0);
      if (s > 0 && m > 0){
        int tp = tg[s-1], tc = tg[s];
        nacc += trans[tp*TT + tc] + ebb[s*TT + tc];
      }
    }
    #pragma unroll
    for (int o = 16; o; o >>= 1){
      nacc += __shfl_xor_sync(0xffffffffu, nacc, o);
      ncnt += __shfl_xor_sync(0xffffffffu, ncnt, o);
    }
    if (lane == 0){ red[eng][wrp] = nacc; ((int*)&red[eng][4])[wrp] = ncnt; }
    asm volatile("bar.sync %0,128;"::"r"(barid):"memory");
    float numv = 0.f;
    if (j == 0){
      float na = red[eng][0] + red[eng][1] + red[eng][2] + red[eng][3];
      int   nc = ((int*)&red[eng][4])[0] + ((int*)&red[eng][4])[1]
               + ((int*)&red[eng][4])[2] + ((int*)&red[eng][4])[3];
      int t0 = tg[0];
      numv = stj /*== startt[0] only if j==0? no: use gather*/;
      numv = startt[t0] + ebb[t0] + na + endt[tg[nc-1]];
    }
    asm volatile("bar.sync %0,128;"::"r"(barid):"memory");

    // ---------------- forward recursion (denominator) ----------------------
    float u = stj + eb[0];          // scores(0) = start + em[:,0,:]
    float C = 0.f;
    if (j == 0) kbuf[eng][0] = u;   // initial renormalizer

    // 2-deep emission/mask prefetch
    float emA = eb[TT];
    float emB = eb[2*TT];
    int   mkA = mb[1];
    int   mkB = mb[2];

    #pragma unroll 2
    for (int s = 1; s < SS; ++s){
      // ---- phase A: publish p_j = exp(u_j) ----
      float p = fex2(u * L2E);
      pbuf[eng][s&1][j] = p;

      float emN = 0.f; int mkN = 0;
      if (s + 2 < SS){ emN = eb[(s+2)*TT]; mkN = mb[s+2]; }

      asm volatile("bar.sync %0,128;"::"r"(barid):"memory");

      // ---- phase B: GEMV acc_j = sum_i p_i * E_ij (f32x2, 4 acc chains) ---
      unsigned long long a0=0ull, a1=0ull, a2=0ull, a3=0ull;
      const uint32_t pb = pb0 + (uint32_t)((s&1)*(TT*4));
      #pragma unroll
      for (int q = 0; q < 26; ++q){
        unsigned long long p01, p23;
        asm volatile("ld.shared.v2.b64 {%0,%1},[%2];"
                     :"=l"(p01),"=l"(p23):"r"(pb + q*16));
        if (q & 1){ FMA2(a2, E2[2*q], p01, a2); FMA2(a3, E2[2*q+1], p23, a3); }
        else      { FMA2(a0, E2[2*q], p01, a0); FMA2(a1, E2[2*q+1], p23, a1); }
      }
      #pragma unroll
      for (int q = 0; q < SME_QUADS; ++q){
        unsigned long long p01, p23, e01, e23;
        asm volatile("ld.shared.v2.b64 {%0,%1},[%2];"
                     :"=l"(p01),"=l"(p23):"r"(pb + (26+q)*16));
        asm volatile("ld.shared.v2.b64 {%0,%1},[%2];"
                     :"=l"(e01),"=l"(e23):"r"(sEb + q*(TT*16)));
        if (q & 1){ FMA2(a2, e01, p01, a2); FMA2(a3, e23, p23, a3); }
        else      { FMA2(a0, e01, p01, a0); FMA2(a1, e23, p23, a1); }
      }
      float K = kbuf[eng][(s-1)&1];   // renormalizer from previous step
      ADD2(a0,a0,a2); ADD2(a1,a1,a3); ADD2(a0,a0,a1);
      float lo, hi;
      asm("mov.b64 {%0,%1},%2;":"=f"(lo),"=f"(hi):"l"(a0));
      float acc = lo + hi;

      float v = fmaf(flg2(acc), LN2, emA);   // em_j + log(acc_j)
      if (mkA > 0){ u = v - K; C += K; }     // masked update
      if (j == 0) kbuf[eng][s&1] = u;        // publish next renormalizer

      emA = emB; emB = emN; mkA = mkB; mkB = mkN;
    }

    // ---- final: denom_b = C + logsumexp_j(u_j + end_j) (exact max) --------
    float w = u + endj;
    float m = w;
    #pragma unroll
    for (int o = 16; o; o >>= 1) m = fmaxf(m, __shfl_xor_sync(0xffffffffu, m, o));
    if (lane == 0) red[eng][wrp] = m;
    asm volatile("bar.sync %0,128;"::"r"(barid):"memory");
    m = fmaxf(fmaxf(red[eng][0], red[eng][1]), fmaxf(red[eng][2], red[eng][3]));
    float e = fex2((w - m) * L2E);
    #pragma unroll
    for (int o = 16; o; o >>= 1) e += __shfl_xor_sync(0xffffffffu, e, o);
    if (lane == 0) red[eng][4 + wrp] = e;
    asm volatile("bar.sync %0,128;"::"r"(barid):"memory");
    if (j == 0){
      float ssum = red[eng][4] + red[eng][5] + red[eng][6] + red[eng][7];
      float denomv = C + m + flg2(ssum) * LN2;
      g_res[b] = numv - denomv;
    }
  }
}

// ---------------------------------------------------------------------------
// Deterministic final reduction: out = sum_b g_res[b]
// ---------------------------------------------------------------------------
__global__ void crf_final(float* out)
{
  __shared__ float sm[256];
  int t = threadIdx.x;
  float a = 0.f;
  for (int b = t; b < BB; b += 256) a += g_res[b];
  sm[t] = a; __syncthreads();
  #pragma unroll
  for (int o = 128; o; o >>= 1){
    if (t < o) sm[t] += sm[t + o];
    __syncthreads();
  }
  if (t == 0) out[0] = sm[0];
}

extern "C" void kernel_launch(void* const* d_in, const int* in_sizes, int n_in,
                              void* d_out, int out_size)
{
  const float* em    = (const float*)d_in[0];
  const int*   tags  = (const int*)  d_in[1];
  const int*   mask  = (const int*)  d_in[2];
  const float* st    = (const float*)d_in[3];
  const float* en    = (const float*)d_in[4];
  const float* tr    = (const float*)d_in[5];
  float* out = (float*)d_out;

  crf_forward<<<GRID_F, 384>>>(em, tags, mask, st, en, tr);
  crf_final<<<1, 256>>>(out);
}

// round 7
// speedup vs baseline: 1.6795x; 1.6795x over previous
#include <cuda_runtime.h>
#include <cstdint>

// Problem constants
#define TT 128
#define SS 512
#define BB 512
#define GRID_F 148           // one CTA per SM, single wave
#define ENG 2                // 128-thread engines per CTA (256 thr -> 256 regs/thr)
#define NENG (GRID_F*ENG)    // 296 engines; each handles 2 batches -> 592 slots

__device__ float g_res[BB];  // per-batch (numerator - denominator)

__device__ __forceinline__ float fex2(float x){ float r; asm("ex2.approx.f32 %0,%1;":"=f"(r):"f"(x)); return r; }
__device__ __forceinline__ float flg2(float x){ float r; asm("lg2.approx.f32 %0,%1;":"=f"(r):"f"(x)); return r; }

#define FMA2(d,a,b,c) asm("fma.rn.f32x2 %0,%1,%2,%3;":"=l"(d):"l"(a),"l"(b),"l"(c))
#define ADD2(d,a,b)   asm("add.rn.f32x2 %0,%1,%2;":"=l"(d):"l"(a),"l"(b))

#define L2E 1.4426950408889634f
#define LN2 0.6931471805599453f

// ---------------------------------------------------------------------------
// Forward algorithm + numerator. One 128-thread engine handles TWO batch
// sequences simultaneously through a single 511-step pass. Thread j owns
// column E[:,j] = exp(trans[:,j]) as 64 f32x2 register pairs, shared by both
// batches' GEMVs. Per step: p_i = exp(u_i) broadcast via smem (per batch);
// acc_j = sum_i p_i*E_ij with packed f32x2 FMAs; u'_j = em_j + log(acc_j) - K,
// C += K, K = thread 0's u from the previous step (delayed renormalizer).
// ---------------------------------------------------------------------------
__global__ void __launch_bounds__(256,1) crf_forward(
    const float* __restrict__ em, const int* __restrict__ tags,
    const int* __restrict__ mask, const float* __restrict__ startt,
    const float* __restrict__ endt, const float* __restrict__ trans)
{
  __shared__ float pbuf[ENG][2][2][TT];   // [eng][batch][phase][j]
  __shared__ float kbuf[ENG][2][2];       // [eng][batch][phase]
  __shared__ float red[ENG][8];

  const int tid  = threadIdx.x;
  const int eng  = tid >> 7;      // 0..1
  const int j    = tid & 127;     // state index owned by this thread
  const int lane = tid & 31;
  const int wrp  = (tid & 127) >> 5;
  const int barid = eng + 1;      // named barrier per engine

  // ---- per-thread register E pairs, full column: i in [0,128) ----
  unsigned long long E2[64];
  #pragma unroll
  for (int q = 0; q < 64; ++q){
    float e0 = fex2(trans[(2*q  )*TT + j] * L2E);
    float e1 = fex2(trans[(2*q+1)*TT + j] * L2E);
    unsigned long long pk;
    asm("mov.b64 %0,{%1,%2};":"=l"(pk):"f"(e0),"f"(e1));
    E2[q] = pk;
  }
  const float endj = endt[j];
  const float stj  = startt[j];

  const uint32_t pA0 = (uint32_t)__cvta_generic_to_shared(&pbuf[eng][0][0][0]);
  const uint32_t pB0 = (uint32_t)__cvta_generic_to_shared(&pbuf[eng][1][0][0]);

  // Engine ge handles batches b0 = ge and b1 = ge + NENG (if valid).
  const int ge = eng*GRID_F + blockIdx.x;       // 0..295
  const int b0 = ge;
  const int b1v = ge + NENG;
  const bool has1 = (b1v < BB);
  const int b1 = has1 ? b1v : 0;                // dummy -> batch 0 data, no write

  const float* eA = em + (long long)b0*SS*TT;   // batch bases
  const float* eB = em + (long long)b1*SS*TT;
  const int*   mA = mask + b0*SS;
  const int*   mB = mask + b1*SS;

  // ---------------- numerator (gather path scores), trivial cost ----------
  float num0 = 0.f, num1 = 0.f;
  #pragma unroll
  for (int bt = 0; bt < 2; ++bt){
    const int b = bt ? b1 : b0;
    const int*   tg  = tags + b*SS;
    const int*   mb  = bt ? mB : mA;
    const float* ebb = bt ? eB : eA;
    float nacc = 0.f; int ncnt = 0;
    for (int s = j; s < SS; s += TT){
      int m = mb[s];
      ncnt += (m > 0);
      if (s > 0 && m > 0){
        int tp = tg[s-1], tc = tg[s];
        nacc += trans[tp*TT + tc] + ebb[s*TT + tc];
      }
    }
    #pragma unroll
    for (int o = 16; o; o >>= 1){
      nacc += __shfl_xor_sync(0xffffffffu, nacc, o);
      ncnt += __shfl_xor_sync(0xffffffffu, ncnt, o);
    }
    if (lane == 0){ red[eng][wrp] = nacc; ((int*)&red[eng][4])[wrp] = ncnt; }
    asm volatile("bar.sync %0,128;"::"r"(barid):"memory");
    if (j == 0){
      float na = red[eng][0] + red[eng][1] + red[eng][2] + red[eng][3];
      int   nc = ((int*)&red[eng][4])[0] + ((int*)&red[eng][4])[1]
               + ((int*)&red[eng][4])[2] + ((int*)&red[eng][4])[3];
      int t0 = tg[0];
      float nv = startt[t0] + ebb[t0] + na + endt[tg[nc-1]];
      if (bt) num1 = nv; else num0 = nv;
    }
    asm volatile("bar.sync %0,128;"::"r"(barid):"memory");
  }

  // ---------------- dual forward recursion (denominators) ------------------
  const float* c0 = eA + j;      // column-j views
  const float* c1 = eB + j;

  float u0 = stj + c0[0];
  float u1 = stj + c1[0];
  float C0 = 0.f, C1 = 0.f;
  if (j == 0){ kbuf[eng][0][0] = u0; kbuf[eng][1][0] = u1; }

  // 2-deep emission/mask prefetch, both batches
  float emA0 = c0[TT],   emA1 = c1[TT];
  float emB0 = c0[2*TT], emB1 = c1[2*TT];
  int   mkA0 = mA[1],    mkA1 = mB[1];
  int   mkB0 = mA[2],    mkB1 = mB[2];

  for (int s = 1; s < SS; ++s){
    // ---- phase A: publish p = exp(u) for both batches ----
    float p0 = fex2(u0 * L2E);
    float p1 = fex2(u1 * L2E);
    const int ph = s & 1;
    pbuf[eng][0][ph][j] = p0;
    pbuf[eng][1][ph][j] = p1;

    float emN0 = 0.f, emN1 = 0.f; int mkN0 = 0, mkN1 = 0;
    if (s + 2 < SS){
      emN0 = c0[(s+2)*TT]; emN1 = c1[(s+2)*TT];
      mkN0 = mA[s+2];      mkN1 = mB[s+2];
    }

    asm volatile("bar.sync %0,128;"::"r"(barid):"memory");

    // ---- phase B: dual GEMV, E2 registers shared by both batches ----
    unsigned long long x0=0ull,x1=0ull,x2=0ull,x3=0ull;   // batch 0 chains
    unsigned long long y0=0ull,y1=0ull,y2=0ull,y3=0ull;   // batch 1 chains
    const uint32_t a0addr = pA0 + (uint32_t)(ph*(TT*4));
    const uint32_t a1addr = pB0 + (uint32_t)(ph*(TT*4));
    #pragma unroll
    for (int q = 0; q < 32; ++q){
      unsigned long long p01a, p23a, p01b, p23b;
      asm volatile("ld.shared.v2.b64 {%0,%1},[%2];"
                   :"=l"(p01a),"=l"(p23a):"r"(a0addr + q*16));
      asm volatile("ld.shared.v2.b64 {%0,%1},[%2];"
                   :"=l"(p01b),"=l"(p23b):"r"(a1addr + q*16));
      if (q & 1){
        FMA2(x2, E2[2*q], p01a, x2); FMA2(x3, E2[2*q+1], p23a, x3);
        FMA2(y2, E2[2*q], p01b, y2); FMA2(y3, E2[2*q+1], p23b, y3);
      } else {
        FMA2(x0, E2[2*q], p01a, x0); FMA2(x1, E2[2*q+1], p23a, x1);
        FMA2(y0, E2[2*q], p01b, y0); FMA2(y1, E2[2*q+1], p23b, y1);
      }
    }
    float K0 = kbuf[eng][0][ph^1];
    float K1 = kbuf[eng][1][ph^1];

    ADD2(x0,x0,x2); ADD2(x1,x1,x3); ADD2(x0,x0,x1);
    ADD2(y0,y0,y2); ADD2(y1,y1,y3); ADD2(y0,y0,y1);
    float lo0, hi0, lo1, hi1;
    asm("mov.b64 {%0,%1},%2;":"=f"(lo0),"=f"(hi0):"l"(x0));
    asm("mov.b64 {%0,%1},%2;":"=f"(lo1),"=f"(hi1):"l"(y0));
    float acc0 = lo0 + hi0;
    float acc1 = lo1 + hi1;

    float v0 = fmaf(flg2(acc0), LN2, emA0);
    float v1 = fmaf(flg2(acc1), LN2, emA1);
    if (mkA0 > 0){ u0 = v0 - K0; C0 += K0; }
    if (mkA1 > 0){ u1 = v1 - K1; C1 += K1; }
    if (j == 0){ kbuf[eng][0][ph] = u0; kbuf[eng][1][ph] = u1; }

    emA0 = emB0; emB0 = emN0; mkA0 = mkB0; mkB0 = mkN0;
    emA1 = emB1; emB1 = emN1; mkA1 = mkB1; mkB1 = mkN1;
  }

  // ---- final: denom_b = C + logsumexp_j(u_j + end_j) (exact max) ----------
  #pragma unroll
  for (int bt = 0; bt < 2; ++bt){
    float w = (bt ? u1 : u0) + endj;
    float m = w;
    #pragma unroll
    for (int o = 16; o; o >>= 1) m = fmaxf(m, __shfl_xor_sync(0xffffffffu, m, o));
    if (lane == 0) red[eng][wrp] = m;
    asm volatile("bar.sync %0,128;"::"r"(barid):"memory");
    m = fmaxf(fmaxf(red[eng][0], red[eng][1]), fmaxf(red[eng][2], red[eng][3]));
    float e = fex2((w - m) * L2E);
    #pragma unroll
    for (int o = 16; o; o >>= 1) e += __shfl_xor_sync(0xffffffffu, e, o);
    if (lane == 0) red[eng][4 + wrp] = e;
    asm volatile("bar.sync %0,128;"::"r"(barid):"memory");
    if (j == 0){
      float ssum = red[eng][4] + red[eng][5] + red[eng][6] + red[eng][7];
      float denomv = (bt ? C1 : C0) + m + flg2(ssum) * LN2;
      if (bt){ if (has1) g_res[b1] = num1 - denomv; }
      else   { g_res[b0] = num0 - denomv; }
    }
    asm volatile("bar.sync %0,128;"::"r"(barid):"memory");
  }
}

// ---------------------------------------------------------------------------
// Deterministic final reduction: out = sum_b g_res[b]
// ---------------------------------------------------------------------------
__global__ void crf_final(float* out)
{
  __shared__ float sm[256];
  int t = threadIdx.x;
  float a = 0.f;
  for (int b = t; b < BB; b += 256) a += g_res[b];
  sm[t] = a; __syncthreads();
  #pragma unroll
  for (int o = 128; o; o >>= 1){
    if (t < o) sm[t] += sm[t + o];
    __syncthreads();
  }
  if (t == 0) out[0] = sm[0];
}

extern "C" void kernel_launch(void* const* d_in, const int* in_sizes, int n_in,
                              void* d_out, int out_size)
{
  const float* em    = (const float*)d_in[0];
  const int*   tags  = (const int*)  d_in[1];
  const int*   mask  = (const int*)  d_in[2];
  const float* st    = (const float*)d_in[3];
  const float* en    = (const float*)d_in[4];
  const float* tr    = (const float*)d_in[5];
  float* out = (float*)d_out;

  crf_forward<<<GRID_F, 256>>>(em, tags, mask, st, en, tr);
  crf_final<<<1, 256>>>(out);
}

// round 10
// speedup vs baseline: 1.7072x; 1.0165x over previous
#include <cuda_runtime.h>
#include <cstdint>

// Problem constants
#define TT 128
#define SS 512
#define BB 512
#define GRID_F 148           // one CTA per SM, single wave
#define ENG 2                // 128-thread engines per CTA (256 thr)
#define NENG (GRID_F*ENG)    // 296 engines; each handles 2 batches -> 592 slots

__device__ float g_res[BB];  // per-batch (numerator - denominator)

__device__ __forceinline__ float fex2(float x){ float r; asm("ex2.approx.f32 %0,%1;":"=f"(r):"f"(x)); return r; }
__device__ __forceinline__ float flg2(float x){ float r; asm("lg2.approx.f32 %0,%1;":"=f"(r):"f"(x)); return r; }

#define FMA2(d,a,b,c) asm("fma.rn.f32x2 %0,%1,%2,%3;":"=l"(d):"l"(a),"l"(b),"l"(c))
#define ADD2(d,a,b)   asm("add.rn.f32x2 %0,%1,%2;":"=l"(d):"l"(a),"l"(b))
#define UNPK(lo_,hi_,v) asm("mov.b64 {%0,%1},%2;":"=f"(lo_),"=f"(hi_):"l"(v))

#define L2E 1.4426950408889634f
#define LN2 0.6931471805599453f

// ---------------------------------------------------------------------------
// Engine = 128 threads handling TWO batches. Thread t owns state t, and holds
// E columns {g, g+64} (g = t&63) over i-half [64h, 64h+64) (h = t>>6) as 64
// f32x2 register pairs. Each p-quad LDS feeds 4 FMA2 (2 cols x 2 batches) ->
// 4:1 FMA:LDS ratio. Per step: GEMV partials -> 8B smem exchange with the
// partner half-thread (t^64) -> combine, log, masked update with delayed
// renormalizer K (state 0's previous u), publish p for next step. 2 bars/step.
// ---------------------------------------------------------------------------
__global__ void __launch_bounds__(256,1) crf_forward(
    const float* __restrict__ em, const int* __restrict__ tags,
    const int* __restrict__ mask, const float* __restrict__ startt,
    const float* __restrict__ endt, const float* __restrict__ trans)
{
  __shared__ __align__(16) float pbuf[ENG][2][2][TT];  // [eng][batch][phase][i]
  __shared__ float2 xbuf[ENG][TT];                     // partial exchange
  __shared__ float  kbuf[ENG][2][2];                   // [eng][batch][phase]
  __shared__ float  red[ENG][8];

  const int tid  = threadIdx.x;
  const int eng  = tid >> 7;      // 0..1
  const int t    = tid & 127;     // owned state
  const int g    = t & 63;        // column group
  const int h    = t >> 6;        // i-half
  const int lane = tid & 31;
  const int wrp  = t >> 5;
  const int barid = eng + 1;
  const int i0   = h << 6;        // this thread's i-range start

  // ---- E register columns: Ea = col g, Eb = col g+64, rows [i0, i0+64) ----
  unsigned long long Ea[32], Eb[32];
  #pragma unroll
  for (int q = 0; q < 32; ++q){
    float a0 = fex2(trans[(i0+2*q  )*TT + g     ] * L2E);
    float a1 = fex2(trans[(i0+2*q+1)*TT + g     ] * L2E);
    float b0 = fex2(trans[(i0+2*q  )*TT + g + 64] * L2E);
    float b1 = fex2(trans[(i0+2*q+1)*TT + g + 64] * L2E);
    asm("mov.b64 %0,{%1,%2};":"=l"(Ea[q]):"f"(a0),"f"(a1));
    asm("mov.b64 %0,{%1,%2};":"=l"(Eb[q]):"f"(b0),"f"(b1));
  }
  const float endj = endt[t];
  const float stj  = startt[t];

  const int ge  = eng*GRID_F + blockIdx.x;   // 0..295
  const int b0  = ge;
  const int b1v = ge + NENG;
  const bool has1 = (b1v < BB);
  const int b1  = has1 ? b1v : 0;

  const float* e0b = em + (long long)b0*SS*TT;
  const float* e1b = em + (long long)b1*SS*TT;
  const int*   mA  = mask + b0*SS;
  const int*   mB  = mask + b1*SS;

  // ---------------- numerator (gather path scores), trivial cost -----------
  float num0 = 0.f, num1 = 0.f;
  #pragma unroll
  for (int bt = 0; bt < 2; ++bt){
    const int b = bt ? b1 : b0;
    const int*   tg  = tags + b*SS;
    const int*   mb  = bt ? mB : mA;
    const float* ebb = bt ? e1b : e0b;
    float nacc = 0.f; int ncnt = 0;
    for (int s = t; s < SS; s += TT){
      int m = mb[s];
      ncnt += (m > 0);
      if (s > 0 && m > 0){
        int tp = tg[s-1], tc = tg[s];
        nacc += trans[tp*TT + tc] + ebb[s*TT + tc];
      }
    }
    #pragma unroll
    for (int o = 16; o; o >>= 1){
      nacc += __shfl_xor_sync(0xffffffffu, nacc, o);
      ncnt += __shfl_xor_sync(0xffffffffu, ncnt, o);
    }
    if (lane == 0){ red[eng][wrp] = nacc; ((int*)&red[eng][4])[wrp] = ncnt; }
    asm volatile("bar.sync %0,128;"::"r"(barid):"memory");
    if (t == 0){
      float na = red[eng][0] + red[eng][1] + red[eng][2] + red[eng][3];
      int   nc = ((int*)&red[eng][4])[0] + ((int*)&red[eng][4])[1]
               + ((int*)&red[eng][4])[2] + ((int*)&red[eng][4])[3];
      int t0 = tg[0];
      float nv = startt[t0] + ebb[t0] + na + endt[tg[nc-1]];
      if (bt) num1 = nv; else num0 = nv;
    }
    asm volatile("bar.sync %0,128;"::"r"(barid):"memory");
  }

  // ---------------- dual forward recursion ---------------------------------
  float u0 = stj + e0b[t];
  float u1 = stj + e1b[t];
  float C0 = 0.f, C1 = 0.f;
  pbuf[eng][0][1][t] = fex2(u0 * L2E);     // p for step 1 (phase 1)
  pbuf[eng][1][1][t] = fex2(u1 * L2E);
  if (t == 0){ kbuf[eng][0][0] = u0; kbuf[eng][1][0] = u1; }

  float emA0 = e0b[TT   + t], emA1 = e1b[TT   + t];
  float emB0 = e0b[2*TT + t], emB1 = e1b[2*TT + t];
  int   mkA0 = mA[1], mkA1 = mB[1];
  int   mkB0 = mA[2], mkB1 = mB[2];

  for (int s = 1; s < SS; ++s){
    const int ph = s & 1;
    asm volatile("bar.sync %0,128;"::"r"(barid):"memory");  // p(s) ready

    const ulonglong2* pA = (const ulonglong2*)&pbuf[eng][0][ph][i0];
    const ulonglong2* pB = (const ulonglong2*)&pbuf[eng][1][ph][i0];

    // 8 chains: (col g / col g+64) x (batch0/batch1) x 2
    unsigned long long ga0=0,ga1=0,gb0=0,gb1=0, ha0=0,ha1=0,hb0=0,hb1=0;
    #pragma unroll
    for (int q = 0; q < 16; ++q){
      ulonglong2 pa = pA[q];     // (p_i,p_i+1),(p_i+2,p_i+3) batch0
      ulonglong2 pb = pB[q];     // batch1
      FMA2(ga0, Ea[2*q  ], pa.x, ga0);
      FMA2(ga1, Ea[2*q+1], pa.y, ga1);
      FMA2(ha0, Eb[2*q  ], pa.x, ha0);
      FMA2(ha1, Eb[2*q+1], pa.y, ha1);
      FMA2(gb0, Ea[2*q  ], pb.x, gb0);
      FMA2(gb1, Ea[2*q+1], pb.y, gb1);
      FMA2(hb0, Eb[2*q  ], pb.x, hb0);
      FMA2(hb1, Eb[2*q+1], pb.y, hb1);
    }
    ADD2(ga0,ga0,ga1); ADD2(gb0,gb0,gb1);
    ADD2(ha0,ha0,ha1); ADD2(hb0,hb0,hb1);
    float l0,h0_,l1,h1_,l2,h2_,l3,h3_;
    UNPK(l0,h0_,ga0); UNPK(l1,h1_,gb0); UNPK(l2,h2_,ha0); UNPK(l3,h3_,hb0);
    float sg0 = l0 + h0_;   // col g,    batch0 partial
    float sg1 = l1 + h1_;   // col g,    batch1 partial
    float sh0 = l2 + h2_;   // col g+64, batch0 partial
    float sh1 = l3 + h3_;   // col g+64, batch1 partial

    // send partial of NON-owned state to partner t^64
    xbuf[eng][t ^ 64] = make_float2(h ? sg0 : sh0, h ? sg1 : sh1);

    // prefetch step s+2 inputs
    float emN0 = 0.f, emN1 = 0.f; int mkN0 = 0, mkN1 = 0;
    if (s + 2 < SS){
      emN0 = e0b[(s+2)*TT + t]; emN1 = e1b[(s+2)*TT + t];
      mkN0 = mA[s+2];           mkN1 = mB[s+2];
    }

    asm volatile("bar.sync %0,128;"::"r"(barid):"memory");  // partials ready

    float2 rc  = xbuf[eng][t];
    float acc0 = (h ? sh0 : sg0) + rc.x;
    float acc1 = (h ? sh1 : sg1) + rc.y;
    float K0 = kbuf[eng][0][ph^1];
    float K1 = kbuf[eng][1][ph^1];

    float v0 = fmaf(flg2(acc0), LN2, emA0);
    float v1 = fmaf(flg2(acc1), LN2, emA1);
    if (mkA0 > 0){ u0 = v0 - K0; if (t == 0) C0 += K0; }
    if (mkA1 > 0){ u1 = v1 - K1; if (t == 0) C1 += K1; }

    pbuf[eng][0][ph^1][t] = fex2(u0 * L2E);   // p for step s+1
    pbuf[eng][1][ph^1][t] = fex2(u1 * L2E);
    if (t == 0){ kbuf[eng][0][ph] = u0; kbuf[eng][1][ph] = u1; }

    emA0 = emB0; emB0 = emN0; mkA0 = mkB0; mkB0 = mkN0;
    emA1 = emB1; emB1 = emN1; mkA1 = mkB1; mkB1 = mkN1;
  }

  // ---- final: denom_b = C + logsumexp_t(u_t + end_t) (exact max) ----------
  #pragma unroll
  for (int bt = 0; bt < 2; ++bt){
    float w = (bt ? u1 : u0) + endj;
    float m = w;
    #pragma unroll
    for (int o = 16; o; o >>= 1) m = fmaxf(m, __shfl_xor_sync(0xffffffffu, m, o));
    if (lane == 0) red[eng][wrp] = m;
    asm volatile("bar.sync %0,128;"::"r"(barid):"memory");
    m = fmaxf(fmaxf(red[eng][0], red[eng][1]), fmaxf(red[eng][2], red[eng][3]));
    float e = fex2((w - m) * L2E);
    #pragma unroll
    for (int o = 16; o; o >>= 1) e += __shfl_xor_sync(0xffffffffu, e, o);
    if (lane == 0) red[eng][4 + wrp] = e;
    asm volatile("bar.sync %0,128;"::"r"(barid):"memory");
    if (t == 0){
      float ssum = red[eng][4] + red[eng][5] + red[eng][6] + red[eng][7];
      float denomv = (bt ? C1 : C0) + m + flg2(ssum) * LN2;
      if (bt){ if (has1) g_res[b1] = num1 - denomv; }
      else   { g_res[b0] = num0 - denomv; }
    }
    asm volatile("bar.sync %0,128;"::"r"(barid):"memory");
  }
}

// ---------------------------------------------------------------------------
// Deterministic final reduction: out = sum_b g_res[b]
// ---------------------------------------------------------------------------
__global__ void crf_final(float* out)
{
  __shared__ float sm[256];
  int t = threadIdx.x;
  float a = 0.f;
  for (int b = t; b < BB; b += 256) a += g_res[b];
  sm[t] = a; __syncthreads();
  #pragma unroll
  for (int o = 128; o; o >>= 1){
    if (t < o) sm[t] += sm[t + o];
    __syncthreads();
  }
  if (t == 0) out[0] = sm[0];
}

extern "C" void kernel_launch(void* const* d_in, const int* in_sizes, int n_in,
                              void* d_out, int out_size)
{
  const float* em    = (const float*)d_in[0];
  const int*   tags  = (const int*)  d_in[1];
  const int*   mask  = (const int*)  d_in[2];
  const float* st    = (const float*)d_in[3];
  const float* en    = (const float*)d_in[4];
  const float* tr    = (const float*)d_in[5];
  float* out = (float*)d_out;

  crf_forward<<<GRID_F, 256>>>(em, tags, mask, st, en, tr);
  crf_final<<<1, 256>>>(out);
}